// round 1
// baseline (speedup 1.0000x reference)
#include <cuda_runtime.h>
#include <math.h>

#define NN 5000
#define EE 40000
#define EP (NN + EE)       // 45000 edges incl self loops
#define HH 8
#define MAXDIN 516
#define MAXC 512
#define MAXHC 4096

// ---------------- scratch (device globals: sanctioned alloc-free scratch) ----
__device__ float g_h[NN * MAXHC];        // per-layer h = af @ W   (~82MB)
__device__ float g_af[NN * MAXDIN];      // concatenated layer input
__device__ float g_f[NN * MAXC];         // selu(feat) of previous layer
__device__ float g_alpha[EP * HH];       // logits -> exp -> alpha (in place)
__device__ float g_es[NN * HH];
__device__ float g_ed[NN * HH];
__device__ float g_m[NN * HH];
__device__ float g_sum[NN * HH];
__device__ float g_c1[NN * 2];
__device__ float g_c2[NN * 2];
__device__ float g_c3[NN * 2];
__device__ int   g_src[EP];
__device__ int   g_dst[EP];
__device__ int   g_deg[NN + 1];
__device__ int   g_off[NN + 1];
__device__ int   g_cur[NN];
__device__ int   g_eidx[EP];
__device__ float g_ws[MAXDIN * HH];
__device__ float g_wd[MAXDIN * HH];

__device__ __forceinline__ float selu_f(float x) {
    const float sc = 1.0507009873554804934193349852946f;
    const float al = 1.6732632423543772848170429916717f;
    return x > 0.f ? sc * x : sc * al * expm1f(x);
}

__device__ __forceinline__ void atomicMaxF(float* addr, float val) {
    int old = __float_as_int(*addr);
    while (__int_as_float(old) < val) {
        int prev = atomicCAS((int*)addr, old, __float_as_int(val));
        if (prev == old) break;
        old = prev;
    }
}

// ---------------- graph setup ----------------------------------------------
__global__ void k_init_deg(int n) {
    int i = blockIdx.x * blockDim.x + threadIdx.x;
    if (i <= n) g_deg[i] = 0;
}

__global__ void k_build_edges(const int* __restrict__ ei, int E, int n) {
    int e = blockIdx.x * blockDim.x + threadIdx.x;
    if (e < E) { g_src[e] = ei[e]; g_dst[e] = ei[E + e]; }
    else if (e < E + n) { g_src[e] = e - E; g_dst[e] = e - E; }
}

__global__ void k_count(int Etot) {
    int e = blockIdx.x * blockDim.x + threadIdx.x;
    if (e < Etot) atomicAdd(&g_deg[g_dst[e]], 1);
}

// single-block exclusive scan (n <= 8191)
__global__ void k_scan(int n) {
    __shared__ int s[1024];
    int tid = threadIdx.x;
    int PER = n / 1024 + 1;
    int base = tid * PER;
    int vals[8];
    int local = 0;
    for (int i = 0; i < PER; i++) {
        int id = base + i;
        int v = (id < n) ? g_deg[id] : 0;
        vals[i] = v; local += v;
    }
    s[tid] = local; __syncthreads();
    for (int d = 1; d < 1024; d <<= 1) {
        int v = s[tid];
        int add = (tid >= d) ? s[tid - d] : 0;
        __syncthreads();
        s[tid] = v + add;
        __syncthreads();
    }
    int run = (tid == 0) ? 0 : s[tid - 1];
    for (int i = 0; i < PER; i++) {
        int id = base + i;
        if (id <= n) { g_off[id] = run; if (id < n) g_cur[id] = run; }
        run += vals[i];
    }
}

__global__ void k_scatter(int Etot) {
    int e = blockIdx.x * blockDim.x + threadIdx.x;
    if (e < Etot) {
        int d = g_dst[e];
        int pos = atomicAdd(&g_cur[d], 1);
        g_eidx[pos] = e;
    }
}

// ---------------- feat0 = selu(data @ W0 + b0) ------------------------------
__global__ void k_feat0(const float* __restrict__ data, const float* __restrict__ W0,
                        const float* __restrict__ b0, int n) {
    int idx = blockIdx.x * blockDim.x + threadIdx.x;
    if (idx >= n * 256) return;
    int nn = idx / 256, c = idx % 256;
    float acc = b0[c];
    #pragma unroll
    for (int k = 0; k < 10; k++) acc += data[nn * 10 + k] * W0[k * 256 + c];
    g_f[nn * 256 + c] = selu_f(acc);
}

// ---------------- concat into g_af ------------------------------------------
struct Cat5 { const float* p[5]; int w[5]; int st[5]; };

__global__ void k_concat(Cat5 cs, int cnt, int din, int n) {
    long idx = (long)blockIdx.x * blockDim.x + threadIdx.x;
    long tot = (long)n * din;
    if (idx >= tot) return;
    int row = (int)(idx / din), col = (int)(idx % din);
    float v = 0.f;
    for (int s = 0; s < cnt; s++) {
        if (col < cs.w[s]) { v = cs.p[s][(long)row * cs.st[s] + col]; break; }
        col -= cs.w[s];
    }
    g_af[idx] = v;
}

// ---------------- ws = W @ a_s  (din x H), same for a_d ---------------------
__global__ void k_wsd(const float* __restrict__ W, const float* __restrict__ as,
                      const float* __restrict__ ad, int din, int C) {
    int t = blockIdx.x * blockDim.x + threadIdx.x;
    if (t >= din * HH) return;
    int k = t / HH, h = t % HH;
    const float* wr = W + (long)k * (HH * C) + (long)h * C;
    const float* ar = as + h * C;
    const float* dr = ad + h * C;
    float s = 0.f, d = 0.f;
    for (int c = 0; c < C; c++) { float w = wr[c]; s += w * ar[c]; d += w * dr[c]; }
    g_ws[k * HH + h] = s;
    g_wd[k * HH + h] = d;
}

// ---------------- es/ed = af @ ws / af @ wd ---------------------------------
__global__ void k_esed(int din, int n) {
    int t = blockIdx.x * blockDim.x + threadIdx.x;
    if (t >= n * HH) return;
    int nn = t / HH, h = t % HH;
    const float* af = g_af + (long)nn * din;
    float a = 0.f, b = 0.f;
    for (int k = 0; k < din; k++) {
        float x = af[k];
        a += x * g_ws[k * HH + h];
        b += x * g_wd[k * HH + h];
    }
    g_es[t] = a;
    g_ed[t] = b;
}

// ---------------- attention softmax over dst segments -----------------------
__global__ void k_init_msum(int n) {
    int t = blockIdx.x * blockDim.x + threadIdx.x;
    if (t >= n * HH) return;
    g_m[t] = -INFINITY;
    g_sum[t] = 0.f;
}

__global__ void k_logits_max(int Etot) {
    int t = blockIdx.x * blockDim.x + threadIdx.x;
    if (t >= Etot * HH) return;
    int e = t >> 3, h = t & 7;
    float v = g_es[g_src[e] * HH + h] + g_ed[g_dst[e] * HH + h];
    v = (v >= 0.f) ? v : 0.2f * v;            // leaky_relu 0.2
    g_alpha[t] = v;
    atomicMaxF(&g_m[g_dst[e] * HH + h], v);
}

__global__ void k_exp_sum(int Etot) {
    int t = blockIdx.x * blockDim.x + threadIdx.x;
    if (t >= Etot * HH) return;
    int e = t >> 3, h = t & 7;
    float ex = expf(g_alpha[t] - g_m[g_dst[e] * HH + h]);
    g_alpha[t] = ex;
    atomicAdd(&g_sum[g_dst[e] * HH + h], ex);
}

__global__ void k_norm(int Etot) {
    int t = blockIdx.x * blockDim.x + threadIdx.x;
    if (t >= Etot * HH) return;
    int e = t >> 3, h = t & 7;
    g_alpha[t] /= g_sum[g_dst[e] * HH + h];
}

// ---------------- SGEMM: C[MxNCOL] = A[MxK] * B[KxNCOL] ---------------------
__global__ void __launch_bounds__(256)
k_sgemm(const float* __restrict__ A, const float* __restrict__ B,
        float* __restrict__ C, int M, int K, int NCOL) {
    __shared__ float As[8][132];
    __shared__ float Bs[8][132];
    const int tid = threadIdx.x;
    const int tx = tid & 15, ty = tid >> 4;
    const int row0 = blockIdx.y << 7;
    const int col0 = blockIdx.x << 7;

    float acc[8][8];
    #pragma unroll
    for (int i = 0; i < 8; i++)
        #pragma unroll
        for (int j = 0; j < 8; j++) acc[i][j] = 0.f;

    const int ar = tid >> 1;
    const int ac = (tid & 1) << 2;
    const int bk = tid >> 5;
    const int bc = (tid & 31) << 2;

    for (int k0 = 0; k0 < K; k0 += 8) {
        int grow = row0 + ar;
        #pragma unroll
        for (int i = 0; i < 4; i++) {
            int gk = k0 + ac + i;
            As[ac + i][ar] = (grow < M && gk < K) ? __ldg(&A[(long)grow * K + gk]) : 0.f;
        }
        {
            int gk = k0 + bk;
            int gc = col0 + bc;
            float4 v = make_float4(0.f, 0.f, 0.f, 0.f);
            if (gk < K) {
                if (gc + 3 < NCOL) {
                    v = *(const float4*)(B + (long)gk * NCOL + gc);
                } else {
                    float t0[4] = {0.f, 0.f, 0.f, 0.f};
                    for (int i = 0; i < 4; i++)
                        if (gc + i < NCOL) t0[i] = B[(long)gk * NCOL + gc + i];
                    v = make_float4(t0[0], t0[1], t0[2], t0[3]);
                }
            }
            *(float4*)&Bs[bk][bc] = v;
        }
        __syncthreads();
        #pragma unroll
        for (int kk = 0; kk < 8; kk++) {
            float a[8], b[8];
            *(float4*)(a)     = *(const float4*)&As[kk][ty * 8];
            *(float4*)(a + 4) = *(const float4*)&As[kk][ty * 8 + 4];
            *(float4*)(b)     = *(const float4*)&Bs[kk][tx * 8];
            *(float4*)(b + 4) = *(const float4*)&Bs[kk][tx * 8 + 4];
            #pragma unroll
            for (int i = 0; i < 8; i++)
                #pragma unroll
                for (int j = 0; j < 8; j++)
                    acc[i][j] += a[i] * b[j];
        }
        __syncthreads();
    }
    #pragma unroll
    for (int i = 0; i < 8; i++) {
        int r = row0 + ty * 8 + i;
        if (r < M) {
            #pragma unroll
            for (int j = 0; j < 8; j++) {
                int c = col0 + tx * 8 + j;
                if (c < NCOL) C[(long)r * NCOL + c] = acc[i][j];
            }
        }
    }
}

// ---------------- feature aggregation: f = selu(mean_h sum_e a*h[src] + b) --
__global__ void k_feat_agg(const float* __restrict__ bias, int C, int n) {
    int c = blockIdx.x * blockDim.x + threadIdx.x;
    int nn = blockIdx.y;
    if (c >= C || nn >= n) return;
    int j0 = g_off[nn], j1 = g_off[nn + 1];
    int HC = HH * C;
    float acc = 0.f;
    for (int j = j0; j < j1; j++) {
        int e = g_eidx[j];
        int s = g_src[e];
        const float* hp = g_h + (long)s * HC + c;
        const float* ap = g_alpha + e * HH;
        #pragma unroll
        for (int h = 0; h < HH; h++) acc += ap[h] * hp[h * C];
    }
    acc = acc * 0.125f + bias[c];
    g_f[(long)nn * C + c] = selu_f(acc);
}

// ---------------- coord aggregation + boundary conditions -------------------
__global__ void k_coord(int din, int n, float* __restrict__ outp) {
    int nn = blockIdx.x * blockDim.x + threadIdx.x;
    if (nn >= n) return;
    int j0 = g_off[nn], j1 = g_off[nn + 1];
    float a0 = 0.f, a1 = 0.f;
    for (int j = j0; j < j1; j++) {
        int e = g_eidx[j];
        int s = g_src[e];
        const float* ap = g_alpha + e * HH;
        float am = 0.f;
        #pragma unroll
        for (int h = 0; h < HH; h++) am += ap[h];
        a0 += am * g_af[(long)s * din + 0];
        a1 += am * g_af[(long)s * din + 1];
    }
    float oc0 = 0.2f * 0.125f * a0;
    float oc1 = 0.2f * 0.125f * a1;
    float f0 = g_af[(long)nn * din + 0];
    float f1 = g_af[(long)nn * din + 1];
    // c0 = where(af0==0, 0, where(af0==1, 1, oc0))
    float c0 = (f0 == 0.f) ? 0.f : ((f0 == 1.f) ? 1.f : oc0);
    // c1 = where(af1==1, 1, where(af1==0, 0, oc1))
    float c1 = (f1 == 1.f) ? 1.f : ((f1 == 0.f) ? 0.f : oc1);
    outp[nn * 2 + 0] = c0;
    outp[nn * 2 + 1] = c1;
}

// ---------------- host orchestration ----------------------------------------
static inline int cdiv(int a, int b) { return (a + b - 1) / b; }

extern "C" void kernel_launch(void* const* d_in, const int* in_sizes, int n_in,
                              void* d_out, int out_size) {
    const float* data = (const float*)d_in[0];
    const int*   eidx = (const int*)d_in[1];
    const float* W0   = (const float*)d_in[2];
    const float* b0   = (const float*)d_in[3];
    const float* W[4], *As[4], *Ad[4], *Bi[4];
    for (int i = 0; i < 4; i++) {
        W[i]  = (const float*)d_in[4 + 4 * i];
        As[i] = (const float*)d_in[5 + 4 * i];
        Ad[i] = (const float*)d_in[6 + 4 * i];
        Bi[i] = (const float*)d_in[7 + 4 * i];
    }
    int n = in_sizes[0] / 10;        // 5000
    int E = in_sizes[1] / 2;         // 40000
    int Etot = E + n;                // 45000
    float* out = (float*)d_out;

    // device addresses of mutable-selection buffers
    float *p_f, *p_c1, *p_c2, *p_c3, *p_af, *p_h;
    cudaGetSymbolAddress((void**)&p_f,  g_f);
    cudaGetSymbolAddress((void**)&p_c1, g_c1);
    cudaGetSymbolAddress((void**)&p_c2, g_c2);
    cudaGetSymbolAddress((void**)&p_c3, g_c3);
    cudaGetSymbolAddress((void**)&p_af, g_af);
    cudaGetSymbolAddress((void**)&p_h,  g_h);
    (void)p_af; (void)p_h;

    const int T = 256;

    // --- graph setup ---
    k_init_deg<<<cdiv(n + 1, T), T>>>(n);
    k_build_edges<<<cdiv(Etot, T), T>>>(eidx, E, n);
    k_count<<<cdiv(Etot, T), T>>>(Etot);
    k_scan<<<1, 1024>>>(n);
    k_scatter<<<cdiv(Etot, T), T>>>(Etot);

    // --- feat0 ---
    k_feat0<<<cdiv(n * 256, T), T>>>(data, W0, b0, n);

    const int dins[4]  = {258, 516, 262, 136};
    const int douts[4] = {512, 256, 128, 20};
    float* couts[4] = {p_c1, p_c2, p_c3, out};

    for (int L = 0; L < 4; L++) {
        int din = dins[L], C = douts[L], HC = HH * C;

        // concat af
        Cat5 cs;
        int cnt = 0;
        if (L == 0) {
            cs.p[0] = data; cs.w[0] = 2; cs.st[0] = 10;
            cs.p[1] = p_f;  cs.w[1] = 256; cs.st[1] = 256;
            cnt = 2;
        } else if (L == 1) {
            cs.p[0] = p_c1; cs.w[0] = 2; cs.st[0] = 2;
            cs.p[1] = data; cs.w[1] = 2; cs.st[1] = 10;
            cs.p[2] = p_f;  cs.w[2] = 512; cs.st[2] = 512;
            cnt = 3;
        } else if (L == 2) {
            cs.p[0] = p_c2; cs.w[0] = 2; cs.st[0] = 2;
            cs.p[1] = p_c1; cs.w[1] = 2; cs.st[1] = 2;
            cs.p[2] = data; cs.w[2] = 2; cs.st[2] = 10;
            cs.p[3] = p_f;  cs.w[3] = 256; cs.st[3] = 256;
            cnt = 4;
        } else {
            cs.p[0] = p_c3; cs.w[0] = 2; cs.st[0] = 2;
            cs.p[1] = p_c2; cs.w[1] = 2; cs.st[1] = 2;
            cs.p[2] = p_c1; cs.w[2] = 2; cs.st[2] = 2;
            cs.p[3] = data; cs.w[3] = 2; cs.st[3] = 10;
            cs.p[4] = p_f;  cs.w[4] = 128; cs.st[4] = 128;
            cnt = 5;
        }
        for (int s = cnt; s < 5; s++) { cs.p[s] = data; cs.w[s] = 0; cs.st[s] = 0; }
        k_concat<<<cdiv(n * din, T), T>>>(cs, cnt, din, n);

        // attention logits via precontracted ws/wd (no h needed)
        k_wsd<<<cdiv(din * HH, T), T>>>(W[L], As[L], Ad[L], din, C);
        k_esed<<<cdiv(n * HH, T), T>>>(din, n);

        // h = af @ W  (only needed for feature aggregation; skip on last layer)
        if (L < 3) {
            dim3 grid(cdiv(HC, 128), cdiv(n, 128));
            k_sgemm<<<grid, 256>>>(/*A=*/p_af, W[L], p_h, n, din, HC);
        }

        // softmax over dst segments
        k_init_msum<<<cdiv(n * HH, T), T>>>(n);
        k_logits_max<<<cdiv(Etot * HH, T), T>>>(Etot);
        k_exp_sum<<<cdiv(Etot * HH, T), T>>>(Etot);
        k_norm<<<cdiv(Etot * HH, T), T>>>(Etot);

        // coordinate update
        k_coord<<<cdiv(n, T), T>>>(din, n, couts[L]);

        // feature aggregation (not needed after layer 4)
        if (L < 3) {
            dim3 grid(cdiv(C, 128), n);
            k_feat_agg<<<grid, 128>>>(Bi[L], C, n);
        }
    }
}

// round 7
// speedup vs baseline: 1.6015x; 1.6015x over previous
#include <cuda_runtime.h>
#include <math.h>
#include <stdint.h>

#define NN 5000
#define EE 40000
#define EP (NN + EE)       // 45000 edges incl self loops
#define HH 8
#define MAXDIN 516
#define MAXC 512
#define MAXHC 4096

// ---------------- scratch (device globals: sanctioned alloc-free scratch) ----
__device__ float g_h[NN * MAXHC];        // per-layer h = af @ W   (~82MB)
__device__ float g_af[NN * MAXDIN];      // concatenated layer input
__device__ float g_f[NN * MAXC];         // selu(feat) of previous layer
__device__ float g_alpha[EP * HH];       // logits -> exp -> alpha (in place)
__device__ float g_es[NN * HH];
__device__ float g_ed[NN * HH];
__device__ float g_m[NN * HH];
__device__ float g_sum[NN * HH];
__device__ float g_c1[NN * 2];
__device__ float g_c2[NN * 2];
__device__ float g_c3[NN * 2];
__device__ int   g_src[EP];
__device__ int   g_dst[EP];
__device__ int   g_deg[NN + 1];
__device__ int   g_off[NN + 1];
__device__ int   g_cur[NN];
__device__ int   g_eidx[EP];
__device__ float g_ws[MAXDIN * HH];
__device__ float g_wd[MAXDIN * HH];

__device__ __forceinline__ float selu_f(float x) {
    const float sc = 1.0507009873554804934193349852946f;
    const float al = 1.6732632423543772848170429916717f;
    return x > 0.f ? sc * x : sc * al * expm1f(x);
}

__device__ __forceinline__ void atomicMaxF(float* addr, float val) {
    int old = __float_as_int(*addr);
    while (__int_as_float(old) < val) {
        int prev = atomicCAS((int*)addr, old, __float_as_int(val));
        if (prev == old) break;
        old = prev;
    }
}

// ======================= mma.sync TF32 GEMM =================================
// C[M x NCOL] = A[M x K] @ B[K x NCOL]   (B consumed in native row-major)
// CTA tile 128x128, K-chunk 32. 8 warps: wm in {0,1} (64 rows), wn in {0..3} (32 cols).
// Each warp: 4x4 grid of m16n8k8 TF32 mma fragments.

__device__ __forceinline__ float cvt_tf32(float x) {
    float r;
    asm("cvt.rna.tf32.f32 %0, %1;" : "=f"(r) : "f"(x));
    return r;
}

__device__ __forceinline__ void mma_tf32(float* d, const uint32_t* a, const uint32_t* b) {
    asm volatile(
        "mma.sync.aligned.m16n8k8.row.col.f32.tf32.tf32.f32 "
        "{%0,%1,%2,%3}, {%4,%5,%6,%7}, {%8,%9}, {%0,%1,%2,%3};"
        : "+f"(d[0]), "+f"(d[1]), "+f"(d[2]), "+f"(d[3])
        : "r"(a[0]), "r"(a[1]), "r"(a[2]), "r"(a[3]), "r"(b[0]), "r"(b[1]));
}

#define BM 128
#define BN 128
#define BK 32
#define ASTR 36      // padded floats per A row (bank-conflict-free)
#define BSTR 132     // padded floats per B k-row
#define ABUF (BM * ASTR)            // 4608 floats / buffer
#define BBUF (BK * BSTR)            // 4224 floats / buffer
#define GEMM_SMEM ((2 * ABUF + 2 * BBUF) * 4)   // 70656 bytes

__global__ void __launch_bounds__(256)
k_mma_gemm(const float* __restrict__ A, const float* __restrict__ B,
           float* __restrict__ C, int M, int K, int NCOL) {
    extern __shared__ float sm[];
    float* As = sm;                  // [2][BM][ASTR]
    float* Bs = sm + 2 * ABUF;       // [2][BK][BSTR]

    const int tid = threadIdx.x;
    const int lane = tid & 31;
    const int wid = tid >> 5;
    const int wm = wid >> 2;         // 0..1
    const int wn = wid & 3;          // 0..3
    const int row0 = blockIdx.y * BM;
    const int col0 = blockIdx.x * BN;
    const int nchunk = (K + BK - 1) / BK;

    // A staging: each thread owns k = tid%32 (fixed), rows tid/32 + 8i, i<16/.. (16 elems)
    const int a_k = tid & 31;
    const int a_r0 = tid >> 5;       // 0..7
    // B staging: each thread owns n = (tid%32)*4 (float4), k = tid/32 + 8i, i<4
    const int b_n = (tid & 31) << 2;
    const int b_k0 = tid >> 5;       // 0..7

    float ra[16];
    float4 rb[4];

    float acc[4][4][4];
    #pragma unroll
    for (int mt = 0; mt < 4; mt++)
        #pragma unroll
        for (int nt = 0; nt < 4; nt++)
            #pragma unroll
            for (int j = 0; j < 4; j++) acc[mt][nt][j] = 0.f;

    // ---- global load of chunk c into staging regs ----
    auto gload = [&](int c) {
        int kb = c * BK;
        int gk = kb + a_k;
        bool kok = (gk < K);
        #pragma unroll
        for (int i = 0; i < 16; i++) {
            int grow = row0 + a_r0 + (i << 3);
            ra[i] = (kok && grow < M) ? __ldg(&A[(size_t)grow * K + gk]) : 0.f;
        }
        #pragma unroll
        for (int i = 0; i < 4; i++) {
            int gkk = kb + b_k0 + (i << 3);
            if (gkk < K) {
                rb[i] = *(const float4*)(B + (size_t)gkk * NCOL + col0 + b_n);
            } else {
                rb[i] = make_float4(0.f, 0.f, 0.f, 0.f);
            }
        }
    };

    // ---- store staging regs into smem buffer b (with tf32 rounding) ----
    auto sstore = [&](int bsel) {
        float* ap = As + bsel * ABUF;
        float* bp = Bs + bsel * BBUF;
        #pragma unroll
        for (int i = 0; i < 16; i++)
            ap[(a_r0 + (i << 3)) * ASTR + a_k] = cvt_tf32(ra[i]);
        #pragma unroll
        for (int i = 0; i < 4; i++) {
            float4 v = rb[i];
            v.x = cvt_tf32(v.x); v.y = cvt_tf32(v.y);
            v.z = cvt_tf32(v.z); v.w = cvt_tf32(v.w);
            *(float4*)(bp + (b_k0 + (i << 3)) * BSTR + b_n) = v;
        }
    };

    gload(0);
    sstore(0);
    __syncthreads();

    for (int c = 0; c < nchunk; c++) {
        if (c + 1 < nchunk) gload(c + 1);

        const float* ap = As + (c & 1) * ABUF;
        const float* bp = Bs + (c & 1) * BBUF;
        const int arow = wm * 64 + (lane >> 2);
        const int bcol = wn * 32 + (lane >> 2);
        const int kq = lane & 3;

        #pragma unroll
        for (int kt = 0; kt < 4; kt++) {
            uint32_t af[4][4], bf[4][2];
            int kk = kt * 8 + kq;
            #pragma unroll
            for (int mt = 0; mt < 4; mt++) {
                const float* p = ap + (arow + mt * 16) * ASTR + kk;
                af[mt][0] = __float_as_uint(p[0]);
                af[mt][1] = __float_as_uint(p[8 * ASTR]);
                af[mt][2] = __float_as_uint(p[4]);
                af[mt][3] = __float_as_uint(p[8 * ASTR + 4]);
            }
            #pragma unroll
            for (int nt = 0; nt < 4; nt++) {
                const float* p = bp + kk * BSTR + bcol + nt * 8;
                bf[nt][0] = __float_as_uint(p[0]);
                bf[nt][1] = __float_as_uint(p[4 * BSTR]);
            }
            #pragma unroll
            for (int mt = 0; mt < 4; mt++)
                #pragma unroll
                for (int nt = 0; nt < 4; nt++)
                    mma_tf32(acc[mt][nt], af[mt], bf[nt]);
        }

        if (c + 1 < nchunk) {
            __syncthreads();
            sstore((c + 1) & 1);
            __syncthreads();
        }
    }

    // ---- epilogue ----
    #pragma unroll
    for (int mt = 0; mt < 4; mt++) {
        int r = row0 + wm * 64 + mt * 16 + (lane >> 2);
        #pragma unroll
        for (int nt = 0; nt < 4; nt++) {
            int cc = col0 + wn * 32 + nt * 8 + ((lane & 3) << 1);
            if (r < M)
                *(float2*)(C + (size_t)r * NCOL + cc) = make_float2(acc[mt][nt][0], acc[mt][nt][1]);
            if (r + 8 < M)
                *(float2*)(C + (size_t)(r + 8) * NCOL + cc) = make_float2(acc[mt][nt][2], acc[mt][nt][3]);
        }
    }
}

// ---------------- graph setup ----------------------------------------------
__global__ void k_init_deg(int n) {
    int i = blockIdx.x * blockDim.x + threadIdx.x;
    if (i <= n) g_deg[i] = 0;
}

__global__ void k_build_edges(const int* __restrict__ ei, int E, int n) {
    int e = blockIdx.x * blockDim.x + threadIdx.x;
    if (e < E) { g_src[e] = ei[e]; g_dst[e] = ei[E + e]; }
    else if (e < E + n) { g_src[e] = e - E; g_dst[e] = e - E; }
}

__global__ void k_count(int Etot) {
    int e = blockIdx.x * blockDim.x + threadIdx.x;
    if (e < Etot) atomicAdd(&g_deg[g_dst[e]], 1);
}

// single-block exclusive scan (n <= 8191)
__global__ void k_scan(int n) {
    __shared__ int s[1024];
    int tid = threadIdx.x;
    int PER = n / 1024 + 1;
    int base = tid * PER;
    int vals[8];
    int local = 0;
    for (int i = 0; i < PER; i++) {
        int id = base + i;
        int v = (id < n) ? g_deg[id] : 0;
        vals[i] = v; local += v;
    }
    s[tid] = local; __syncthreads();
    for (int d = 1; d < 1024; d <<= 1) {
        int v = s[tid];
        int add = (tid >= d) ? s[tid - d] : 0;
        __syncthreads();
        s[tid] = v + add;
        __syncthreads();
    }
    int run = (tid == 0) ? 0 : s[tid - 1];
    for (int i = 0; i < PER; i++) {
        int id = base + i;
        if (id <= n) { g_off[id] = run; if (id < n) g_cur[id] = run; }
        run += vals[i];
    }
}

__global__ void k_scatter(int Etot) {
    int e = blockIdx.x * blockDim.x + threadIdx.x;
    if (e < Etot) {
        int d = g_dst[e];
        int pos = atomicAdd(&g_cur[d], 1);
        g_eidx[pos] = e;
    }
}

// ---------------- feat0 = selu(data @ W0 + b0) ------------------------------
__global__ void k_feat0(const float* __restrict__ data, const float* __restrict__ W0,
                        const float* __restrict__ b0, int n) {
    int idx = blockIdx.x * blockDim.x + threadIdx.x;
    if (idx >= n * 256) return;
    int nn = idx / 256, c = idx % 256;
    float acc = b0[c];
    #pragma unroll
    for (int k = 0; k < 10; k++) acc += data[nn * 10 + k] * W0[k * 256 + c];
    g_f[nn * 256 + c] = selu_f(acc);
}

// ---------------- concat into g_af ------------------------------------------
struct Cat5 { const float* p[5]; int w[5]; int st[5]; };

__global__ void k_concat(Cat5 cs, int cnt, int din, int n) {
    long idx = (long)blockIdx.x * blockDim.x + threadIdx.x;
    long tot = (long)n * din;
    if (idx >= tot) return;
    int row = (int)(idx / din), col = (int)(idx % din);
    float v = 0.f;
    for (int s = 0; s < cnt; s++) {
        if (col < cs.w[s]) { v = cs.p[s][(long)row * cs.st[s] + col]; break; }
        col -= cs.w[s];
    }
    g_af[idx] = v;
}

// ---------------- ws = W @ a_s  (din x H), same for a_d ---------------------
__global__ void k_wsd(const float* __restrict__ W, const float* __restrict__ as,
                      const float* __restrict__ ad, int din, int C) {
    int t = blockIdx.x * blockDim.x + threadIdx.x;
    if (t >= din * HH) return;
    int k = t / HH, h = t % HH;
    const float* wr = W + (long)k * (HH * C) + (long)h * C;
    const float* ar = as + h * C;
    const float* dr = ad + h * C;
    float s = 0.f, d = 0.f;
    for (int c = 0; c < C; c++) { float w = wr[c]; s += w * ar[c]; d += w * dr[c]; }
    g_ws[k * HH + h] = s;
    g_wd[k * HH + h] = d;
}

// ---------------- es/ed = af @ ws / af @ wd ---------------------------------
__global__ void k_esed(int din, int n) {
    int t = blockIdx.x * blockDim.x + threadIdx.x;
    if (t >= n * HH) return;
    int nn = t / HH, h = t % HH;
    const float* af = g_af + (long)nn * din;
    float a = 0.f, b = 0.f;
    for (int k = 0; k < din; k++) {
        float x = af[k];
        a += x * g_ws[k * HH + h];
        b += x * g_wd[k * HH + h];
    }
    g_es[t] = a;
    g_ed[t] = b;
}

// ---------------- attention softmax over dst segments -----------------------
__global__ void k_init_msum(int n) {
    int t = blockIdx.x * blockDim.x + threadIdx.x;
    if (t >= n * HH) return;
    g_m[t] = -INFINITY;
    g_sum[t] = 0.f;
}

__global__ void k_logits_max(int Etot) {
    int t = blockIdx.x * blockDim.x + threadIdx.x;
    if (t >= Etot * HH) return;
    int e = t >> 3, h = t & 7;
    float v = g_es[g_src[e] * HH + h] + g_ed[g_dst[e] * HH + h];
    v = (v >= 0.f) ? v : 0.2f * v;            // leaky_relu 0.2
    g_alpha[t] = v;
    atomicMaxF(&g_m[g_dst[e] * HH + h], v);
}

__global__ void k_exp_sum(int Etot) {
    int t = blockIdx.x * blockDim.x + threadIdx.x;
    if (t >= Etot * HH) return;
    int e = t >> 3, h = t & 7;
    float ex = expf(g_alpha[t] - g_m[g_dst[e] * HH + h]);
    g_alpha[t] = ex;
    atomicAdd(&g_sum[g_dst[e] * HH + h], ex);
}

__global__ void k_norm(int Etot) {
    int t = blockIdx.x * blockDim.x + threadIdx.x;
    if (t >= Etot * HH) return;
    int e = t >> 3, h = t & 7;
    g_alpha[t] /= g_sum[g_dst[e] * HH + h];
}

// ---------------- feature aggregation: f = selu(mean_h sum_e a*h[src] + b) --
__global__ void k_feat_agg(const float* __restrict__ bias, int C, int n) {
    int c = blockIdx.x * blockDim.x + threadIdx.x;
    int nn = blockIdx.y;
    if (c >= C || nn >= n) return;
    int j0 = g_off[nn], j1 = g_off[nn + 1];
    int HC = HH * C;
    float acc = 0.f;
    for (int j = j0; j < j1; j++) {
        int e = g_eidx[j];
        int s = g_src[e];
        const float* hp = g_h + (long)s * HC + c;
        const float* ap = g_alpha + e * HH;
        #pragma unroll
        for (int h = 0; h < HH; h++) acc += ap[h] * hp[h * C];
    }
    acc = acc * 0.125f + bias[c];
    g_f[(long)nn * C + c] = selu_f(acc);
}

// ---------------- coord aggregation + boundary conditions -------------------
__global__ void k_coord(int din, int n, float* __restrict__ outp) {
    int nn = blockIdx.x * blockDim.x + threadIdx.x;
    if (nn >= n) return;
    int j0 = g_off[nn], j1 = g_off[nn + 1];
    float a0 = 0.f, a1 = 0.f;
    for (int j = j0; j < j1; j++) {
        int e = g_eidx[j];
        int s = g_src[e];
        const float* ap = g_alpha + e * HH;
        float am = 0.f;
        #pragma unroll
        for (int h = 0; h < HH; h++) am += ap[h];
        a0 += am * g_af[(long)s * din + 0];
        a1 += am * g_af[(long)s * din + 1];
    }
    float oc0 = 0.2f * 0.125f * a0;
    float oc1 = 0.2f * 0.125f * a1;
    float f0 = g_af[(long)nn * din + 0];
    float f1 = g_af[(long)nn * din + 1];
    float c0 = (f0 == 0.f) ? 0.f : ((f0 == 1.f) ? 1.f : oc0);
    float c1 = (f1 == 1.f) ? 1.f : ((f1 == 0.f) ? 0.f : oc1);
    outp[nn * 2 + 0] = c0;
    outp[nn * 2 + 1] = c1;
}

// ---------------- host orchestration ----------------------------------------
static inline int cdiv(int a, int b) { return (a + b - 1) / b; }

extern "C" void kernel_launch(void* const* d_in, const int* in_sizes, int n_in,
                              void* d_out, int out_size) {
    const float* data = (const float*)d_in[0];
    const int*   eidx = (const int*)d_in[1];
    const float* W0   = (const float*)d_in[2];
    const float* b0   = (const float*)d_in[3];
    const float* W[4], *As[4], *Ad[4], *Bi[4];
    for (int i = 0; i < 4; i++) {
        W[i]  = (const float*)d_in[4 + 4 * i];
        As[i] = (const float*)d_in[5 + 4 * i];
        Ad[i] = (const float*)d_in[6 + 4 * i];
        Bi[i] = (const float*)d_in[7 + 4 * i];
    }
    int n = in_sizes[0] / 10;        // 5000
    int E = in_sizes[1] / 2;         // 40000
    int Etot = E + n;                // 45000
    float* out = (float*)d_out;

    float *p_f, *p_c1, *p_c2, *p_c3, *p_af, *p_h;
    cudaGetSymbolAddress((void**)&p_f,  g_f);
    cudaGetSymbolAddress((void**)&p_c1, g_c1);
    cudaGetSymbolAddress((void**)&p_c2, g_c2);
    cudaGetSymbolAddress((void**)&p_c3, g_c3);
    cudaGetSymbolAddress((void**)&p_af, g_af);
    cudaGetSymbolAddress((void**)&p_h,  g_h);

    cudaFuncSetAttribute(k_mma_gemm, cudaFuncAttributeMaxDynamicSharedMemorySize, GEMM_SMEM);

    const int T = 256;

    // --- graph setup ---
    k_init_deg<<<cdiv(n + 1, T), T>>>(n);
    k_build_edges<<<cdiv(Etot, T), T>>>(eidx, E, n);
    k_count<<<cdiv(Etot, T), T>>>(Etot);
    k_scan<<<1, 1024>>>(n);
    k_scatter<<<cdiv(Etot, T), T>>>(Etot);

    // --- feat0 ---
    k_feat0<<<cdiv(n * 256, T), T>>>(data, W0, b0, n);

    const int dins[4]  = {258, 516, 262, 136};
    const int douts[4] = {512, 256, 128, 20};
    float* couts[4] = {p_c1, p_c2, p_c3, out};

    for (int L = 0; L < 4; L++) {
        int din = dins[L], C = douts[L], HC = HH * C;

        // concat af
        Cat5 cs;
        int cnt = 0;
        if (L == 0) {
            cs.p[0] = data; cs.w[0] = 2; cs.st[0] = 10;
            cs.p[1] = p_f;  cs.w[1] = 256; cs.st[1] = 256;
            cnt = 2;
        } else if (L == 1) {
            cs.p[0] = p_c1; cs.w[0] = 2; cs.st[0] = 2;
            cs.p[1] = data; cs.w[1] = 2; cs.st[1] = 10;
            cs.p[2] = p_f;  cs.w[2] = 512; cs.st[2] = 512;
            cnt = 3;
        } else if (L == 2) {
            cs.p[0] = p_c2; cs.w[0] = 2; cs.st[0] = 2;
            cs.p[1] = p_c1; cs.w[1] = 2; cs.st[1] = 2;
            cs.p[2] = data; cs.w[2] = 2; cs.st[2] = 10;
            cs.p[3] = p_f;  cs.w[3] = 256; cs.st[3] = 256;
            cnt = 4;
        } else {
            cs.p[0] = p_c3; cs.w[0] = 2; cs.st[0] = 2;
            cs.p[1] = p_c2; cs.w[1] = 2; cs.st[1] = 2;
            cs.p[2] = p_c1; cs.w[2] = 2; cs.st[2] = 2;
            cs.p[3] = data; cs.w[3] = 2; cs.st[3] = 10;
            cs.p[4] = p_f;  cs.w[4] = 128; cs.st[4] = 128;
            cnt = 5;
        }
        for (int s = cnt; s < 5; s++) { cs.p[s] = data; cs.w[s] = 0; cs.st[s] = 0; }
        k_concat<<<cdiv(n * din, T), T>>>(cs, cnt, din, n);

        // attention logits via precontracted ws/wd (no h needed)
        k_wsd<<<cdiv(din * HH, T), T>>>(W[L], As[L], Ad[L], din, C);
        k_esed<<<cdiv(n * HH, T), T>>>(din, n);

        // h = af @ W via mma.sync TF32 (only needed for feature agg; skip last layer)
        if (L < 3) {
            dim3 grid(HC / BN, cdiv(n, BM));
            k_mma_gemm<<<grid, 256, GEMM_SMEM>>>(p_af, W[L], p_h, n, din, HC);
        }

        // softmax over dst segments
        k_init_msum<<<cdiv(n * HH, T), T>>>(n);
        k_logits_max<<<cdiv(Etot * HH, T), T>>>(Etot);
        k_exp_sum<<<cdiv(Etot * HH, T), T>>>(Etot);
        k_norm<<<cdiv(Etot * HH, T), T>>>(Etot);

        // coordinate update
        k_coord<<<cdiv(n, T), T>>>(din, n, couts[L]);

        // feature aggregation (not needed after layer 4)
        if (L < 3) {
            dim3 grid(cdiv(C, 128), n);
            k_feat_agg<<<grid, 128>>>(Bi[L], C, n);
        }
    }
}

// round 10
// speedup vs baseline: 2.1533x; 1.3445x over previous
#include <cuda_runtime.h>
#include <math.h>
#include <stdint.h>

#define NN 5000
#define EE 40000
#define EP (NN + EE)       // 45000 edges incl self loops
#define HH 8
#define MAXDINP 544        // max padded din (516 -> 544)
#define MAXC 512
#define MAXHC 4096

// ---------------- scratch (device globals: sanctioned alloc-free scratch) ----
__device__ float g_h[NN * MAXHC];        // per-layer h = af @ W
__device__ float g_af[NN * MAXDINP];     // concatenated layer input (K-padded)
__device__ float g_f[NN * MAXC];         // selu(feat) of previous layer
__device__ float g_alpha[EP * HH];       // unnormalized exp(logit - max)
__device__ float g_es[NN * HH];
__device__ float g_ed[NN * HH];
__device__ float g_sum[NN * HH];         // per (dst, head) softmax denominators
__device__ float g_c1[NN * 2];
__device__ float g_c2[NN * 2];
__device__ float g_c3[NN * 2];
__device__ int   g_src[EP];
__device__ int   g_dst[EP];
__device__ int   g_deg[NN + 1];
__device__ int   g_off[NN + 1];
__device__ int   g_cur[NN];
__device__ int   g_eidx[EP];
__device__ float g_ws[MAXDINP * HH];
__device__ float g_wd[MAXDINP * HH];

__device__ __forceinline__ float selu_f(float x) {
    const float sc = 1.0507009873554804934193349852946f;
    const float al = 1.6732632423543772848170429916717f;
    return x > 0.f ? sc * x : sc * al * expm1f(x);
}

// ======================= mma.sync TF32 GEMM =================================
// C[M x NCOL] = A[M x Kpad] @ B[K x NCOL]  (A rows padded w/ zeros to Kpad)
// CTA tile 128x128, K-chunk 32, cp.async double buffer, 8 warps (2x4),
// each warp 4x4 m16n8k8 TF32 fragments.

__device__ __forceinline__ void mma_tf32(float* d, const uint32_t* a, const uint32_t* b) {
    asm volatile(
        "mma.sync.aligned.m16n8k8.row.col.f32.tf32.tf32.f32 "
        "{%0,%1,%2,%3}, {%4,%5,%6,%7}, {%8,%9}, {%0,%1,%2,%3};"
        : "+f"(d[0]), "+f"(d[1]), "+f"(d[2]), "+f"(d[3])
        : "r"(a[0]), "r"(a[1]), "r"(a[2]), "r"(a[3]), "r"(b[0]), "r"(b[1]));
}

__device__ __forceinline__ void cp16(uint32_t dst, const void* src, bool pred) {
    uint32_t zf = pred ? 16u : 0u;
    asm volatile("cp.async.cg.shared.global [%0], [%1], 16, %2;"
                 :: "r"(dst), "l"(src), "r"(zf) : "memory");
}

#define BM 128
#define BN 128
#define BK 32
#define ASTR 36      // floats per A smem row (144B: 16B-aligned, conflict-free)
#define BSTR 132     // floats per B smem k-row (528B: 16B-aligned)
#define ABUF (BM * ASTR)            // 4608 floats / buffer
#define BBUF (BK * BSTR)            // 4224 floats / buffer
#define GEMM_SMEM ((2 * ABUF + 2 * BBUF) * 4)   // 70656 bytes

__global__ void __launch_bounds__(256, 2)
k_mma_gemm(const float* __restrict__ A, const float* __restrict__ B,
           float* __restrict__ C, int M, int Kpad, int K, int NCOL) {
    extern __shared__ float sm[];
    float* As = sm;
    float* Bs = sm + 2 * ABUF;
    uint32_t sbase = (uint32_t)__cvta_generic_to_shared(sm);
    uint32_t sA = sbase;
    uint32_t sB = sbase + 2 * ABUF * 4;

    const int tid = threadIdx.x;
    const int lane = tid & 31;
    const int wid = tid >> 5;
    const int wm = wid >> 2;         // 0..1
    const int wn = wid & 3;          // 0..3
    const int row0 = blockIdx.y * BM;
    const int col0 = blockIdx.x * BN;
    const int nchunk = Kpad / BK;

    auto issue = [&](int c, int buf) {
        int kb = c * BK;
        #pragma unroll
        for (int i = 0; i < 4; i++) {          // A: 1024 float4s
            int idx = tid + (i << 8);
            int row = idx >> 3, k4 = idx & 7;
            const float* gp = A + (size_t)(row0 + row) * Kpad + kb + (k4 << 2);
            cp16(sA + (uint32_t)(buf * ABUF + row * ASTR + (k4 << 2)) * 4, gp,
                 row0 + row < M);
        }
        #pragma unroll
        for (int i = 0; i < 4; i++) {          // B: 1024 float4s
            int idx = tid + (i << 8);
            int kr = idx >> 5, n4 = idx & 31;
            int gk = kb + kr;
            const float* gp = B + (size_t)gk * NCOL + col0 + (n4 << 2);
            cp16(sB + (uint32_t)(buf * BBUF + kr * BSTR + (n4 << 2)) * 4, gp,
                 gk < K);
        }
        asm volatile("cp.async.commit_group;" ::: "memory");
    };

    float acc[4][4][4];
    #pragma unroll
    for (int mt = 0; mt < 4; mt++)
        #pragma unroll
        for (int nt = 0; nt < 4; nt++)
            #pragma unroll
            for (int j = 0; j < 4; j++) acc[mt][nt][j] = 0.f;

    issue(0, 0);

    const int arow = wm * 64 + (lane >> 2);
    const int bcol = wn * 32 + (lane >> 2);
    const int kq = lane & 3;

    for (int c = 0; c < nchunk; c++) {
        if (c + 1 < nchunk) {
            issue(c + 1, (c + 1) & 1);
            asm volatile("cp.async.wait_group 1;" ::: "memory");
        } else {
            asm volatile("cp.async.wait_group 0;" ::: "memory");
        }
        __syncthreads();

        const float* ap = As + (c & 1) * ABUF;
        const float* bp = Bs + (c & 1) * BBUF;

        #pragma unroll
        for (int kt = 0; kt < 4; kt++) {
            uint32_t af[4][4], bf[4][2];
            int kk = kt * 8 + kq;
            #pragma unroll
            for (int mt = 0; mt < 4; mt++) {
                const float* p = ap + (arow + mt * 16) * ASTR + kk;
                af[mt][0] = __float_as_uint(p[0]);
                af[mt][1] = __float_as_uint(p[8 * ASTR]);
                af[mt][2] = __float_as_uint(p[4]);
                af[mt][3] = __float_as_uint(p[8 * ASTR + 4]);
            }
            #pragma unroll
            for (int nt = 0; nt < 4; nt++) {
                const float* p = bp + kk * BSTR + bcol + nt * 8;
                bf[nt][0] = __float_as_uint(p[0]);
                bf[nt][1] = __float_as_uint(p[4 * BSTR]);
            }
            #pragma unroll
            for (int mt = 0; mt < 4; mt++)
                #pragma unroll
                for (int nt = 0; nt < 4; nt++)
                    mma_tf32(acc[mt][nt], af[mt], bf[nt]);
        }
        __syncthreads();
    }

    // ---- epilogue ----
    #pragma unroll
    for (int mt = 0; mt < 4; mt++) {
        int r = row0 + wm * 64 + mt * 16 + (lane >> 2);
        #pragma unroll
        for (int nt = 0; nt < 4; nt++) {
            int cc = col0 + wn * 32 + nt * 8 + ((lane & 3) << 1);
            if (r < M)
                *(float2*)(C + (size_t)r * NCOL + cc) = make_float2(acc[mt][nt][0], acc[mt][nt][1]);
            if (r + 8 < M)
                *(float2*)(C + (size_t)(r + 8) * NCOL + cc) = make_float2(acc[mt][nt][2], acc[mt][nt][3]);
        }
    }
}

// ---------------- graph setup ----------------------------------------------
__global__ void k_init_deg(int n) {
    int i = blockIdx.x * blockDim.x + threadIdx.x;
    if (i <= n) g_deg[i] = 0;
}

__global__ void k_build_count(const int* __restrict__ ei, int E, int n) {
    int e = blockIdx.x * blockDim.x + threadIdx.x;
    if (e < E) {
        int s = ei[e], d = ei[E + e];
        g_src[e] = s; g_dst[e] = d;
        atomicAdd(&g_deg[d], 1);
    } else if (e < E + n) {
        int v = e - E;
        g_src[e] = v; g_dst[e] = v;
        atomicAdd(&g_deg[v], 1);
    }
}

// single-block exclusive scan (n <= 8191)
__global__ void k_scan(int n) {
    __shared__ int s[1024];
    int tid = threadIdx.x;
    int PER = n / 1024 + 1;
    int base = tid * PER;
    int vals[8];
    int local = 0;
    for (int i = 0; i < PER; i++) {
        int id = base + i;
        int v = (id < n) ? g_deg[id] : 0;
        vals[i] = v; local += v;
    }
    s[tid] = local; __syncthreads();
    for (int d = 1; d < 1024; d <<= 1) {
        int v = s[tid];
        int add = (tid >= d) ? s[tid - d] : 0;
        __syncthreads();
        s[tid] = v + add;
        __syncthreads();
    }
    int run = (tid == 0) ? 0 : s[tid - 1];
    for (int i = 0; i < PER; i++) {
        int id = base + i;
        if (id <= n) { g_off[id] = run; if (id < n) g_cur[id] = run; }
        run += vals[i];
    }
}

__global__ void k_scatter(int Etot) {
    int e = blockIdx.x * blockDim.x + threadIdx.x;
    if (e < Etot) {
        int d = g_dst[e];
        int pos = atomicAdd(&g_cur[d], 1);
        g_eidx[pos] = e;
    }
}

// ---------------- feat0 = selu(data @ W0 + b0) ------------------------------
__global__ void k_feat0(const float* __restrict__ data, const float* __restrict__ W0,
                        const float* __restrict__ b0, int n) {
    int idx = blockIdx.x * blockDim.x + threadIdx.x;
    if (idx >= n * 256) return;
    int nn = idx / 256, c = idx % 256;
    float acc = b0[c];
    #pragma unroll
    for (int k = 0; k < 10; k++) acc += data[nn * 10 + k] * W0[k * 256 + c];
    g_f[nn * 256 + c] = selu_f(acc);
}

// ---------------- ws = W @ a_s  (din x H), same for a_d ---------------------
__global__ void k_wsd(const float* __restrict__ W, const float* __restrict__ as,
                      const float* __restrict__ ad, int din, int C) {
    int t = blockIdx.x * blockDim.x + threadIdx.x;
    if (t >= din * HH) return;
    int k = t / HH, h = t % HH;
    const float* wr = W + (long)k * (HH * C) + (long)h * C;
    const float* ar = as + h * C;
    const float* dr = ad + h * C;
    float s = 0.f, d = 0.f;
    for (int c = 0; c < C; c++) { float w = wr[c]; s += w * ar[c]; d += w * dr[c]; }
    g_ws[k * HH + h] = s;
    g_wd[k * HH + h] = d;
}

// ---------------- fused concat + es/ed --------------------------------------
// one block per node: build af row in smem (+ write padded g_af), then compute
// es[h] = af . ws[:,h], ed[h] = af . wd[:,h] with 16-lane groups.
struct Cat5 { const float* p[5]; int w[5]; int st[5]; };

__global__ void __launch_bounds__(256)
k_cat_esed(Cat5 cs, int cnt, int din, int dinp, int n) {
    __shared__ float saf[MAXDINP];
    int nn = blockIdx.x;
    int tid = threadIdx.x;
    for (int col = tid; col < dinp; col += 256) {
        float v = 0.f;
        int c = col;
        if (col < din) {
            #pragma unroll 5
            for (int s = 0; s < 5; s++) {
                if (s >= cnt) break;
                if (c < cs.w[s]) { v = cs.p[s][(size_t)nn * cs.st[s] + c]; break; }
                c -= cs.w[s];
            }
        }
        saf[col] = v;
        g_af[(size_t)nn * dinp + col] = v;
    }
    __syncthreads();
    int warp = tid >> 5, lane = tid & 31;
    int o = warp * 2 + (lane >> 4);       // 0..15
    int h = o & 7;
    int sel = o >> 3;
    const float* wv = sel ? g_wd : g_ws;
    float acc = 0.f;
    for (int col = (lane & 15); col < din; col += 16)
        acc += saf[col] * wv[col * 8 + h];
    acc += __shfl_xor_sync(0xffffffffu, acc, 1);
    acc += __shfl_xor_sync(0xffffffffu, acc, 2);
    acc += __shfl_xor_sync(0xffffffffu, acc, 4);
    acc += __shfl_xor_sync(0xffffffffu, acc, 8);
    if ((lane & 15) == 0) {
        if (sel) g_ed[nn * 8 + h] = acc;
        else     g_es[nn * 8 + h] = acc;
    }
}

// ---------------- fused softmax (per dst segment) + coord update ------------
// one warp per dst node. lane = h + 8*jj: 8 heads x 4 edge-slices.
// writes unnormalized ex -> g_alpha, per-head sums -> g_sum, coord -> outp.
__global__ void k_softmax_coord(int dinp, int n, float* __restrict__ outp) {
    int w = blockIdx.x * 8 + (threadIdx.x >> 5);
    if (w >= n) return;
    int lane = threadIdx.x & 31;
    int h = lane & 7, jj = lane >> 3;
    int j0 = g_off[w], j1 = g_off[w + 1];
    int deg = j1 - j0;
    float edv = g_ed[w * 8 + h];
    float mx = -1e30f, sum = 0.f, a0 = 0.f, a1 = 0.f;

    if (deg <= 32) {
        float lv[8]; int le[8];
        int cnt = 0;
        for (int j = j0 + jj; j < j1; j += 4) {
            int e = g_eidx[j];
            float v = g_es[g_src[e] * 8 + h] + edv;
            v = v >= 0.f ? v : 0.2f * v;
            lv[cnt] = v; le[cnt] = e; cnt++;
            mx = fmaxf(mx, v);
        }
        mx = fmaxf(mx, __shfl_xor_sync(0xffffffffu, mx, 8));
        mx = fmaxf(mx, __shfl_xor_sync(0xffffffffu, mx, 16));
        for (int i = 0; i < cnt; i++) {
            int e = le[i];
            float ex = __expf(lv[i] - mx);
            g_alpha[e * 8 + h] = ex;
            sum += ex;
            int s = g_src[e];
            a0 += ex * g_af[(size_t)s * dinp];
            a1 += ex * g_af[(size_t)s * dinp + 1];
        }
    } else {
        for (int j = j0 + jj; j < j1; j += 4) {
            int e = g_eidx[j];
            float v = g_es[g_src[e] * 8 + h] + edv;
            v = v >= 0.f ? v : 0.2f * v;
            g_alpha[e * 8 + h] = v;
            mx = fmaxf(mx, v);
        }
        mx = fmaxf(mx, __shfl_xor_sync(0xffffffffu, mx, 8));
        mx = fmaxf(mx, __shfl_xor_sync(0xffffffffu, mx, 16));
        for (int j = j0 + jj; j < j1; j += 4) {
            int e = g_eidx[j];
            float ex = __expf(g_alpha[e * 8 + h] - mx);
            g_alpha[e * 8 + h] = ex;
            sum += ex;
            int s = g_src[e];
            a0 += ex * g_af[(size_t)s * dinp];
            a1 += ex * g_af[(size_t)s * dinp + 1];
        }
    }

    sum += __shfl_xor_sync(0xffffffffu, sum, 8);
    sum += __shfl_xor_sync(0xffffffffu, sum, 16);
    if (jj == 0) g_sum[w * 8 + h] = sum;

    a0 /= sum; a1 /= sum;
    #pragma unroll
    for (int d = 16; d >= 1; d >>= 1) {
        a0 += __shfl_xor_sync(0xffffffffu, a0, d);
        a1 += __shfl_xor_sync(0xffffffffu, a1, d);
    }
    if (lane == 0) {
        float oc0 = 0.025f * a0;     // 0.2 / 8
        float oc1 = 0.025f * a1;
        float f0 = g_af[(size_t)w * dinp];
        float f1 = g_af[(size_t)w * dinp + 1];
        float c0 = (f0 == 0.f) ? 0.f : ((f0 == 1.f) ? 1.f : oc0);
        float c1 = (f1 == 1.f) ? 1.f : ((f1 == 0.f) ? 0.f : oc1);
        outp[w * 2 + 0] = c0;
        outp[w * 2 + 1] = c1;
    }
}

// ---------------- feature aggregation ---------------------------------------
// f[nn,c] = selu( (1/8) * sum_h (1/sum_h) sum_e ex[e,h] * h[src_e, h*C+c] + b )
__global__ void __launch_bounds__(128)
k_feat_agg(const float* __restrict__ bias, int C, int n, int HC) {
    int c4 = blockIdx.x * blockDim.x + threadIdx.x;
    int nn = blockIdx.y;
    if (c4 >= (C >> 2)) return;
    int c = c4 << 2;
    int j0 = g_off[nn], j1 = g_off[nn + 1];
    float4 acc[HH];
    #pragma unroll
    for (int h = 0; h < HH; h++) acc[h] = make_float4(0.f, 0.f, 0.f, 0.f);
    for (int j = j0; j < j1; j++) {
        int e = g_eidx[j];
        int s = g_src[e];
        float4 al0 = *(const float4*)(g_alpha + e * 8);
        float4 al1 = *(const float4*)(g_alpha + e * 8 + 4);
        float aw[8] = {al0.x, al0.y, al0.z, al0.w, al1.x, al1.y, al1.z, al1.w};
        const float* hp = g_h + (size_t)s * HC + c;
        #pragma unroll
        for (int h = 0; h < HH; h++) {
            float4 hv = *(const float4*)(hp + h * C);
            acc[h].x += aw[h] * hv.x;
            acc[h].y += aw[h] * hv.y;
            acc[h].z += aw[h] * hv.z;
            acc[h].w += aw[h] * hv.w;
        }
    }
    const float* sp = g_sum + nn * 8;
    float4 r = make_float4(0.f, 0.f, 0.f, 0.f);
    #pragma unroll
    for (int h = 0; h < HH; h++) {
        float inv = 1.f / sp[h];
        r.x += acc[h].x * inv;
        r.y += acc[h].y * inv;
        r.z += acc[h].z * inv;
        r.w += acc[h].w * inv;
    }
    float4 b4 = *(const float4*)(bias + c);
    r.x = selu_f(r.x * 0.125f + b4.x);
    r.y = selu_f(r.y * 0.125f + b4.y);
    r.z = selu_f(r.z * 0.125f + b4.z);
    r.w = selu_f(r.w * 0.125f + b4.w);
    *(float4*)(g_f + (size_t)nn * C + c) = r;
}

// ---------------- host orchestration ----------------------------------------
static inline int cdiv(int a, int b) { return (a + b - 1) / b; }

extern "C" void kernel_launch(void* const* d_in, const int* in_sizes, int n_in,
                              void* d_out, int out_size) {
    const float* data = (const float*)d_in[0];
    const int*   eidx = (const int*)d_in[1];
    const float* W0   = (const float*)d_in[2];
    const float* b0   = (const float*)d_in[3];
    const float* W[4], *As[4], *Ad[4], *Bi[4];
    for (int i = 0; i < 4; i++) {
        W[i]  = (const float*)d_in[4 + 4 * i];
        As[i] = (const float*)d_in[5 + 4 * i];
        Ad[i] = (const float*)d_in[6 + 4 * i];
        Bi[i] = (const float*)d_in[7 + 4 * i];
    }
    int n = in_sizes[0] / 10;        // 5000
    int E = in_sizes[1] / 2;         // 40000
    int Etot = E + n;                // 45000
    float* out = (float*)d_out;

    float *p_f, *p_c1, *p_c2, *p_c3, *p_af, *p_h;
    cudaGetSymbolAddress((void**)&p_f,  g_f);
    cudaGetSymbolAddress((void**)&p_c1, g_c1);
    cudaGetSymbolAddress((void**)&p_c2, g_c2);
    cudaGetSymbolAddress((void**)&p_c3, g_c3);
    cudaGetSymbolAddress((void**)&p_af, g_af);
    cudaGetSymbolAddress((void**)&p_h,  g_h);

    cudaFuncSetAttribute(k_mma_gemm, cudaFuncAttributeMaxDynamicSharedMemorySize, GEMM_SMEM);

    const int T = 256;

    // --- graph setup ---
    k_init_deg<<<cdiv(n + 1, T), T>>>(n);
    k_build_count<<<cdiv(Etot, T), T>>>(eidx, E, n);
    k_scan<<<1, 1024>>>(n);
    k_scatter<<<cdiv(Etot, T), T>>>(Etot);

    // --- feat0 ---
    k_feat0<<<cdiv(n * 256, T), T>>>(data, W0, b0, n);

    const int dins[4]  = {258, 516, 262, 136};
    const int dinps[4] = {288, 544, 288, 160};   // padded to 32
    const int douts[4] = {512, 256, 128, 20};
    float* couts[4] = {p_c1, p_c2, p_c3, out};

    for (int L = 0; L < 4; L++) {
        int din = dins[L], dinp = dinps[L], C = douts[L], HC = HH * C;

        // attention weight precontraction (independent of af)
        k_wsd<<<cdiv(din * HH, T), T>>>(W[L], As[L], Ad[L], din, C);

        // concat af + es/ed in one pass
        Cat5 cs;
        int cnt = 0;
        if (L == 0) {
            cs.p[0] = data; cs.w[0] = 2; cs.st[0] = 10;
            cs.p[1] = p_f;  cs.w[1] = 256; cs.st[1] = 256;
            cnt = 2;
        } else if (L == 1) {
            cs.p[0] = p_c1; cs.w[0] = 2; cs.st[0] = 2;
            cs.p[1] = data; cs.w[1] = 2; cs.st[1] = 10;
            cs.p[2] = p_f;  cs.w[2] = 512; cs.st[2] = 512;
            cnt = 3;
        } else if (L == 2) {
            cs.p[0] = p_c2; cs.w[0] = 2; cs.st[0] = 2;
            cs.p[1] = p_c1; cs.w[1] = 2; cs.st[1] = 2;
            cs.p[2] = data; cs.w[2] = 2; cs.st[2] = 10;
            cs.p[3] = p_f;  cs.w[3] = 256; cs.st[3] = 256;
            cnt = 4;
        } else {
            cs.p[0] = p_c3; cs.w[0] = 2; cs.st[0] = 2;
            cs.p[1] = p_c2; cs.w[1] = 2; cs.st[1] = 2;
            cs.p[2] = p_c1; cs.w[2] = 2; cs.st[2] = 2;
            cs.p[3] = data; cs.w[3] = 2; cs.st[3] = 10;
            cs.p[4] = p_f;  cs.w[4] = 128; cs.st[4] = 128;
            cnt = 5;
        }
        for (int s = cnt; s < 5; s++) { cs.p[s] = data; cs.w[s] = 0; cs.st[s] = 0; }
        k_cat_esed<<<n, 256>>>(cs, cnt, din, dinp, n);

        // h = af @ W via mma.sync TF32 (skip last layer: only coords needed)
        if (L < 3) {
            dim3 grid(HC / BN, cdiv(n, BM));
            k_mma_gemm<<<grid, 256, GEMM_SMEM>>>(p_af, W[L], p_h, n, dinp, din, HC);
        }

        // fused segment softmax + coordinate update
        k_softmax_coord<<<cdiv(n, 8), 256>>>(dinp, n, couts[L]);

        // feature aggregation (not needed after layer 4)
        if (L < 3) {
            dim3 grid(cdiv(C / 4, 128), n);
            k_feat_agg<<<grid, 128>>>(Bi[L], C, n, HC);
        }
    }
}

// round 11
// speedup vs baseline: 2.8822x; 1.3385x over previous
#include <cuda_runtime.h>
#include <math.h>
#include <stdint.h>

#define NN 5000
#define EE 40000
#define EP (NN + EE)       // 45000 edges incl self loops
#define HH 8
#define MAXDINP 544        // max padded din (516 -> 544)
#define MAXC 512
#define MAXHC 4096

// ---------------- scratch (device globals: sanctioned alloc-free scratch) ----
__device__ float g_h[NN * MAXHC];        // per-layer h = af @ W; also A2 for fused L1
__device__ float g_af[NN * MAXDINP];     // concatenated layer input (K-padded)
__device__ float g_f[NN * MAXC];         // selu(feat) of previous layer
__device__ float g_alpha[EP * HH];       // unnormalized exp(logit - max)
__device__ float g_es[NN * HH];
__device__ float g_ed[NN * HH];
__device__ float g_sum[NN * HH];         // per (dst, head) softmax denominators
__device__ float g_c1[NN * 2];
__device__ float g_c2[NN * 2];
__device__ float g_c3[NN * 2];
__device__ int   g_src[EP];
__device__ int   g_dst[EP];
__device__ int   g_deg[NN + 1];
__device__ int   g_off[NN + 1];
__device__ int   g_cur[NN];
__device__ int   g_eidx[EP];
__device__ float g_ws[MAXDINP * HH];
__device__ float g_wd[MAXDINP * HH];
__device__ float g_b2[8 * 288 * 512];    // repacked W for fused L1 GEMM (4.7MB)

__device__ __forceinline__ float selu_f(float x) {
    const float sc = 1.0507009873554804934193349852946f;
    const float al = 1.6732632423543772848170429916717f;
    return x > 0.f ? sc * x : sc * al * expm1f(x);
}

// ======================= mma.sync TF32 GEMM =================================
// C[M x NCOL] = A[M x Kpad] @ B[K x NCOL]  (A rows padded w/ zeros to Kpad)
// CTA tile 128x128, K-chunk 32, cp.async double buffer, 8 warps (2x4),
// each warp 4x4 m16n8k8 TF32 fragments.
// fuse=1: out = selu(0.125*acc + bias[c]) (fused feature epilogue)

__device__ __forceinline__ void mma_tf32(float* d, const uint32_t* a, const uint32_t* b) {
    asm volatile(
        "mma.sync.aligned.m16n8k8.row.col.f32.tf32.tf32.f32 "
        "{%0,%1,%2,%3}, {%4,%5,%6,%7}, {%8,%9}, {%0,%1,%2,%3};"
        : "+f"(d[0]), "+f"(d[1]), "+f"(d[2]), "+f"(d[3])
        : "r"(a[0]), "r"(a[1]), "r"(a[2]), "r"(a[3]), "r"(b[0]), "r"(b[1]));
}

__device__ __forceinline__ void cp16(uint32_t dst, const void* src, bool pred) {
    uint32_t zf = pred ? 16u : 0u;
    asm volatile("cp.async.cg.shared.global [%0], [%1], 16, %2;"
                 :: "r"(dst), "l"(src), "r"(zf) : "memory");
}

#define BM 128
#define BN 128
#define BK 32
#define ASTR 36
#define BSTR 132
#define ABUF (BM * ASTR)
#define BBUF (BK * BSTR)
#define GEMM_SMEM ((2 * ABUF + 2 * BBUF) * 4)   // 70656 bytes

__global__ void __launch_bounds__(256, 2)
k_mma_gemm(const float* __restrict__ A, const float* __restrict__ B,
           float* __restrict__ C, int M, int Kpad, int K, int NCOL,
           int fuse, const float* __restrict__ bias) {
    extern __shared__ float sm[];
    float* As = sm;
    float* Bs = sm + 2 * ABUF;
    uint32_t sbase = (uint32_t)__cvta_generic_to_shared(sm);
    uint32_t sA = sbase;
    uint32_t sB = sbase + 2 * ABUF * 4;

    const int tid = threadIdx.x;
    const int lane = tid & 31;
    const int wid = tid >> 5;
    const int wm = wid >> 2;
    const int wn = wid & 3;
    const int row0 = blockIdx.y * BM;
    const int col0 = blockIdx.x * BN;
    const int nchunk = Kpad / BK;

    auto issue = [&](int c, int buf) {
        int kb = c * BK;
        #pragma unroll
        for (int i = 0; i < 4; i++) {
            int idx = tid + (i << 8);
            int row = idx >> 3, k4 = idx & 7;
            const float* gp = A + (size_t)(row0 + row) * Kpad + kb + (k4 << 2);
            cp16(sA + (uint32_t)(buf * ABUF + row * ASTR + (k4 << 2)) * 4, gp,
                 row0 + row < M);
        }
        #pragma unroll
        for (int i = 0; i < 4; i++) {
            int idx = tid + (i << 8);
            int kr = idx >> 5, n4 = idx & 31;
            int gk = kb + kr;
            const float* gp = B + (size_t)gk * NCOL + col0 + (n4 << 2);
            cp16(sB + (uint32_t)(buf * BBUF + kr * BSTR + (n4 << 2)) * 4, gp,
                 gk < K);
        }
        asm volatile("cp.async.commit_group;" ::: "memory");
    };

    float acc[4][4][4];
    #pragma unroll
    for (int mt = 0; mt < 4; mt++)
        #pragma unroll
        for (int nt = 0; nt < 4; nt++)
            #pragma unroll
            for (int j = 0; j < 4; j++) acc[mt][nt][j] = 0.f;

    issue(0, 0);

    const int arow = wm * 64 + (lane >> 2);
    const int bcol = wn * 32 + (lane >> 2);
    const int kq = lane & 3;

    for (int c = 0; c < nchunk; c++) {
        if (c + 1 < nchunk) {
            issue(c + 1, (c + 1) & 1);
            asm volatile("cp.async.wait_group 1;" ::: "memory");
        } else {
            asm volatile("cp.async.wait_group 0;" ::: "memory");
        }
        __syncthreads();

        const float* ap = As + (c & 1) * ABUF;
        const float* bp = Bs + (c & 1) * BBUF;

        #pragma unroll
        for (int kt = 0; kt < 4; kt++) {
            uint32_t af[4][4], bf[4][2];
            int kk = kt * 8 + kq;
            #pragma unroll
            for (int mt = 0; mt < 4; mt++) {
                const float* p = ap + (arow + mt * 16) * ASTR + kk;
                af[mt][0] = __float_as_uint(p[0]);
                af[mt][1] = __float_as_uint(p[8 * ASTR]);
                af[mt][2] = __float_as_uint(p[4]);
                af[mt][3] = __float_as_uint(p[8 * ASTR + 4]);
            }
            #pragma unroll
            for (int nt = 0; nt < 4; nt++) {
                const float* p = bp + kk * BSTR + bcol + nt * 8;
                bf[nt][0] = __float_as_uint(p[0]);
                bf[nt][1] = __float_as_uint(p[4 * BSTR]);
            }
            #pragma unroll
            for (int mt = 0; mt < 4; mt++)
                #pragma unroll
                for (int nt = 0; nt < 4; nt++)
                    mma_tf32(acc[mt][nt], af[mt], bf[nt]);
        }
        __syncthreads();
    }

    // ---- epilogue ----
    #pragma unroll
    for (int mt = 0; mt < 4; mt++) {
        int r = row0 + wm * 64 + mt * 16 + (lane >> 2);
        #pragma unroll
        for (int nt = 0; nt < 4; nt++) {
            int cc = col0 + wn * 32 + nt * 8 + ((lane & 3) << 1);
            float v0 = acc[mt][nt][0], v1 = acc[mt][nt][1];
            float v2 = acc[mt][nt][2], v3 = acc[mt][nt][3];
            if (fuse) {
                float b0 = bias[cc], b1 = bias[cc + 1];
                v0 = selu_f(v0 * 0.125f + b0);
                v1 = selu_f(v1 * 0.125f + b1);
                v2 = selu_f(v2 * 0.125f + b0);
                v3 = selu_f(v3 * 0.125f + b1);
            }
            if (r < M)
                *(float2*)(C + (size_t)r * NCOL + cc) = make_float2(v0, v1);
            if (r + 8 < M)
                *(float2*)(C + (size_t)(r + 8) * NCOL + cc) = make_float2(v2, v3);
        }
    }
}

// ---------------- graph setup ----------------------------------------------
__global__ void k_init_deg(int n) {
    int i = blockIdx.x * blockDim.x + threadIdx.x;
    if (i <= n) g_deg[i] = 0;
}

__global__ void k_build_count(const int* __restrict__ ei, int E, int n) {
    int e = blockIdx.x * blockDim.x + threadIdx.x;
    if (e < E) {
        int s = ei[e], d = ei[E + e];
        g_src[e] = s; g_dst[e] = d;
        atomicAdd(&g_deg[d], 1);
    } else if (e < E + n) {
        int v = e - E;
        g_src[e] = v; g_dst[e] = v;
        atomicAdd(&g_deg[v], 1);
    }
}

// single-block exclusive scan (n <= 8191)
__global__ void k_scan(int n) {
    __shared__ int s[1024];
    int tid = threadIdx.x;
    int PER = n / 1024 + 1;
    int base = tid * PER;
    int vals[8];
    int local = 0;
    for (int i = 0; i < PER; i++) {
        int id = base + i;
        int v = (id < n) ? g_deg[id] : 0;
        vals[i] = v; local += v;
    }
    s[tid] = local; __syncthreads();
    for (int d = 1; d < 1024; d <<= 1) {
        int v = s[tid];
        int add = (tid >= d) ? s[tid - d] : 0;
        __syncthreads();
        s[tid] = v + add;
        __syncthreads();
    }
    int run = (tid == 0) ? 0 : s[tid - 1];
    for (int i = 0; i < PER; i++) {
        int id = base + i;
        if (id <= n) { g_off[id] = run; if (id < n) g_cur[id] = run; }
        run += vals[i];
    }
}

__global__ void k_scatter(int Etot) {
    int e = blockIdx.x * blockDim.x + threadIdx.x;
    if (e < Etot) {
        int d = g_dst[e];
        int pos = atomicAdd(&g_cur[d], 1);
        g_eidx[pos] = e;
    }
}

// ---------------- feat0 = selu(data @ W0 + b0) ------------------------------
__global__ void k_feat0(const float* __restrict__ data, const float* __restrict__ W0,
                        const float* __restrict__ b0, int n) {
    int idx = blockIdx.x * blockDim.x + threadIdx.x;
    if (idx >= n * 256) return;
    int nn = idx / 256, c = idx % 256;
    float acc = b0[c];
    #pragma unroll
    for (int k = 0; k < 10; k++) acc += data[nn * 10 + k] * W0[k * 256 + c];
    g_f[nn * 256 + c] = selu_f(acc);
}

// ---------------- ws = W @ a_s (warp per (k,h), coalesced) ------------------
__global__ void k_wsd(const float* __restrict__ W, const float* __restrict__ as,
                      const float* __restrict__ ad, int din, int C, int HC) {
    int gw = (blockIdx.x * blockDim.x + threadIdx.x) >> 5;
    int lane = threadIdx.x & 31;
    if (gw >= din * 8) return;
    int k = gw >> 3, h = gw & 7;
    const float* wr = W + (size_t)k * HC + h * C;
    const float* ar = as + h * C;
    const float* dr = ad + h * C;
    float s = 0.f, d = 0.f;
    for (int c = lane; c < C; c += 32) {
        float w = wr[c];
        s += w * ar[c];
        d += w * dr[c];
    }
    #pragma unroll
    for (int o = 16; o >= 1; o >>= 1) {
        s += __shfl_xor_sync(0xffffffffu, s, o);
        d += __shfl_xor_sync(0xffffffffu, d, o);
    }
    if (lane == 0) { g_ws[k * 8 + h] = s; g_wd[k * 8 + h] = d; }
}

// ---------------- fused concat + es/ed --------------------------------------
struct Cat5 { const float* p[5]; int w[5]; int st[5]; };

__global__ void __launch_bounds__(256)
k_cat_esed(Cat5 cs, int cnt, int din, int dinp, int n) {
    __shared__ float saf[MAXDINP];
    int nn = blockIdx.x;
    int tid = threadIdx.x;
    for (int col = tid; col < dinp; col += 256) {
        float v = 0.f;
        int c = col;
        if (col < din) {
            #pragma unroll 5
            for (int s = 0; s < 5; s++) {
                if (s >= cnt) break;
                if (c < cs.w[s]) { v = cs.p[s][(size_t)nn * cs.st[s] + c]; break; }
                c -= cs.w[s];
            }
        }
        saf[col] = v;
        g_af[(size_t)nn * dinp + col] = v;
    }
    __syncthreads();
    int warp = tid >> 5, lane = tid & 31;
    int o = warp * 2 + (lane >> 4);
    int h = o & 7;
    int sel = o >> 3;
    const float* wv = sel ? g_wd : g_ws;
    float acc = 0.f;
    for (int col = (lane & 15); col < din; col += 16)
        acc += saf[col] * wv[col * 8 + h];
    acc += __shfl_xor_sync(0xffffffffu, acc, 1);
    acc += __shfl_xor_sync(0xffffffffu, acc, 2);
    acc += __shfl_xor_sync(0xffffffffu, acc, 4);
    acc += __shfl_xor_sync(0xffffffffu, acc, 8);
    if ((lane & 15) == 0) {
        if (sel) g_ed[nn * 8 + h] = acc;
        else     g_es[nn * 8 + h] = acc;
    }
}

// ---------------- fused softmax (per dst segment) + coord update ------------
__global__ void k_softmax_coord(int dinp, int n, float* __restrict__ outp) {
    int w = blockIdx.x * 8 + (threadIdx.x >> 5);
    if (w >= n) return;
    int lane = threadIdx.x & 31;
    int h = lane & 7, jj = lane >> 3;
    int j0 = g_off[w], j1 = g_off[w + 1];
    int deg = j1 - j0;
    float edv = g_ed[w * 8 + h];
    float mx = -1e30f, sum = 0.f, a0 = 0.f, a1 = 0.f;

    if (deg <= 32) {
        float lv[8]; int le[8];
        int cnt = 0;
        for (int j = j0 + jj; j < j1; j += 4) {
            int e = g_eidx[j];
            float v = g_es[g_src[e] * 8 + h] + edv;
            v = v >= 0.f ? v : 0.2f * v;
            lv[cnt] = v; le[cnt] = e; cnt++;
            mx = fmaxf(mx, v);
        }
        mx = fmaxf(mx, __shfl_xor_sync(0xffffffffu, mx, 8));
        mx = fmaxf(mx, __shfl_xor_sync(0xffffffffu, mx, 16));
        for (int i = 0; i < cnt; i++) {
            int e = le[i];
            float ex = __expf(lv[i] - mx);
            g_alpha[e * 8 + h] = ex;
            sum += ex;
            int s = g_src[e];
            a0 += ex * g_af[(size_t)s * dinp];
            a1 += ex * g_af[(size_t)s * dinp + 1];
        }
    } else {
        for (int j = j0 + jj; j < j1; j += 4) {
            int e = g_eidx[j];
            float v = g_es[g_src[e] * 8 + h] + edv;
            v = v >= 0.f ? v : 0.2f * v;
            g_alpha[e * 8 + h] = v;
            mx = fmaxf(mx, v);
        }
        mx = fmaxf(mx, __shfl_xor_sync(0xffffffffu, mx, 8));
        mx = fmaxf(mx, __shfl_xor_sync(0xffffffffu, mx, 16));
        for (int j = j0 + jj; j < j1; j += 4) {
            int e = g_eidx[j];
            float ex = __expf(g_alpha[e * 8 + h] - mx);
            g_alpha[e * 8 + h] = ex;
            sum += ex;
            int s = g_src[e];
            a0 += ex * g_af[(size_t)s * dinp];
            a1 += ex * g_af[(size_t)s * dinp + 1];
        }
    }

    sum += __shfl_xor_sync(0xffffffffu, sum, 8);
    sum += __shfl_xor_sync(0xffffffffu, sum, 16);
    if (jj == 0) g_sum[w * 8 + h] = sum;

    a0 /= sum; a1 /= sum;
    #pragma unroll
    for (int d = 16; d >= 1; d >>= 1) {
        a0 += __shfl_xor_sync(0xffffffffu, a0, d);
        a1 += __shfl_xor_sync(0xffffffffu, a1, d);
    }
    if (lane == 0) {
        float oc0 = 0.025f * a0;
        float oc1 = 0.025f * a1;
        float f0 = g_af[(size_t)w * dinp];
        float f1 = g_af[(size_t)w * dinp + 1];
        float c0 = (f0 == 0.f) ? 0.f : ((f0 == 1.f) ? 1.f : oc0);
        float c1 = (f1 == 1.f) ? 1.f : ((f1 == 0.f) ? 0.f : oc1);
        outp[w * 2 + 0] = c0;
        outp[w * 2 + 1] = c1;
    }
}

// ---------------- fused L1 path: alpha-weighted af aggregation --------------
// A2[n, h*dinp + col] = (1/sum[n,h]) * sum_e ex[e,h] * af[src_e, col]
// one block per dst node, blockDim = dinp (multiple of 32).
__global__ void k_agg_af(int dinp, int n) {
    __shared__ float sex[64 * 8];
    __shared__ int   ssrc[64];
    __shared__ float sinv[8];
    int nn = blockIdx.x;
    int tid = threadIdx.x;
    int j0 = g_off[nn];
    int deg = g_off[nn + 1] - j0;
    if (tid < 8) sinv[tid] = 1.f / g_sum[nn * 8 + tid];
    float acc[8];
    #pragma unroll
    for (int h = 0; h < 8; h++) acc[h] = 0.f;

    for (int base = 0; base < deg; base += 64) {
        int m = min(64, deg - base);
        __syncthreads();
        if (tid < m) ssrc[tid] = g_src[g_eidx[j0 + base + tid]];
        if (tid < m * 8) {
            int jj = tid >> 3, h = tid & 7;
            sex[tid] = g_alpha[g_eidx[j0 + base + jj] * 8 + h];
        }
        __syncthreads();
        for (int j = 0; j < m; j++) {
            float v = g_af[(size_t)ssrc[j] * dinp + tid];
            const float* ep = &sex[j * 8];
            #pragma unroll
            for (int h = 0; h < 8; h++) acc[h] += ep[h] * v;
        }
    }
    size_t ob = (size_t)nn * (8 * dinp) + tid;
    #pragma unroll
    for (int h = 0; h < 8; h++)
        g_h[ob + h * dinp] = acc[h] * sinv[h];
}

// ---------------- B2 repack: B2[h*dinp+k, c] = W[k, h*C+c] ------------------
__global__ void k_repack_b2(const float* __restrict__ W, int din, int dinp,
                            int C, int HC) {
    int idx = blockIdx.x * 256 + threadIdx.x;
    int total = 8 * dinp * C;
    if (idx >= total) return;
    int c = idx % C;
    int r = idx / C;
    int h = r / dinp, k = r % dinp;
    g_b2[idx] = (k < din) ? W[(size_t)k * HC + h * C + c] : 0.f;
}

// ---------------- feature aggregation (old path, L2/L3) ---------------------
__global__ void k_feat_agg(const float* __restrict__ bias, int C, int n, int HC) {
    int c4 = blockIdx.x * blockDim.x + threadIdx.x;
    int nn = blockIdx.y;
    if (c4 >= (C >> 2)) return;
    int c = c4 << 2;
    int j0 = g_off[nn], j1 = g_off[nn + 1];
    float4 acc[HH];
    #pragma unroll
    for (int h = 0; h < HH; h++) acc[h] = make_float4(0.f, 0.f, 0.f, 0.f);
    for (int j = j0; j < j1; j++) {
        int e = g_eidx[j];
        int s = g_src[e];
        float4 al0 = *(const float4*)(g_alpha + e * 8);
        float4 al1 = *(const float4*)(g_alpha + e * 8 + 4);
        float aw[8] = {al0.x, al0.y, al0.z, al0.w, al1.x, al1.y, al1.z, al1.w};
        const float* hp = g_h + (size_t)s * HC + c;
        #pragma unroll
        for (int h = 0; h < HH; h++) {
            float4 hv = *(const float4*)(hp + h * C);
            acc[h].x += aw[h] * hv.x;
            acc[h].y += aw[h] * hv.y;
            acc[h].z += aw[h] * hv.z;
            acc[h].w += aw[h] * hv.w;
        }
    }
    const float* sp = g_sum + nn * 8;
    float4 r = make_float4(0.f, 0.f, 0.f, 0.f);
    #pragma unroll
    for (int h = 0; h < HH; h++) {
        float inv = 1.f / sp[h];
        r.x += acc[h].x * inv;
        r.y += acc[h].y * inv;
        r.z += acc[h].z * inv;
        r.w += acc[h].w * inv;
    }
    float4 b4 = *(const float4*)(bias + c);
    r.x = selu_f(r.x * 0.125f + b4.x);
    r.y = selu_f(r.y * 0.125f + b4.y);
    r.z = selu_f(r.z * 0.125f + b4.z);
    r.w = selu_f(r.w * 0.125f + b4.w);
    *(float4*)(g_f + (size_t)nn * C + c) = r;
}

// ---------------- host orchestration ----------------------------------------
static inline int cdiv(int a, int b) { return (a + b - 1) / b; }

extern "C" void kernel_launch(void* const* d_in, const int* in_sizes, int n_in,
                              void* d_out, int out_size) {
    const float* data = (const float*)d_in[0];
    const int*   eidx = (const int*)d_in[1];
    const float* W0   = (const float*)d_in[2];
    const float* b0   = (const float*)d_in[3];
    const float* W[4], *As[4], *Ad[4], *Bi[4];
    for (int i = 0; i < 4; i++) {
        W[i]  = (const float*)d_in[4 + 4 * i];
        As[i] = (const float*)d_in[5 + 4 * i];
        Ad[i] = (const float*)d_in[6 + 4 * i];
        Bi[i] = (const float*)d_in[7 + 4 * i];
    }
    int n = in_sizes[0] / 10;        // 5000
    int E = in_sizes[1] / 2;         // 40000
    int Etot = E + n;                // 45000
    float* out = (float*)d_out;

    float *p_f, *p_c1, *p_c2, *p_c3, *p_af, *p_h, *p_b2;
    cudaGetSymbolAddress((void**)&p_f,  g_f);
    cudaGetSymbolAddress((void**)&p_c1, g_c1);
    cudaGetSymbolAddress((void**)&p_c2, g_c2);
    cudaGetSymbolAddress((void**)&p_c3, g_c3);
    cudaGetSymbolAddress((void**)&p_af, g_af);
    cudaGetSymbolAddress((void**)&p_h,  g_h);
    cudaGetSymbolAddress((void**)&p_b2, g_b2);

    cudaFuncSetAttribute(k_mma_gemm, cudaFuncAttributeMaxDynamicSharedMemorySize, GEMM_SMEM);

    const int T = 256;

    // --- graph setup ---
    k_init_deg<<<cdiv(n + 1, T), T>>>(n);
    k_build_count<<<cdiv(Etot, T), T>>>(eidx, E, n);
    k_scan<<<1, 1024>>>(n);
    k_scatter<<<cdiv(Etot, T), T>>>(Etot);

    // --- feat0 ---
    k_feat0<<<cdiv(n * 256, T), T>>>(data, W0, b0, n);

    const int dins[4]  = {258, 516, 262, 136};
    const int dinps[4] = {288, 544, 288, 160};   // padded to 32
    const int douts[4] = {512, 256, 128, 20};
    float* couts[4] = {p_c1, p_c2, p_c3, out};

    for (int L = 0; L < 4; L++) {
        int din = dins[L], dinp = dinps[L], C = douts[L], HC = HH * C;

        // attention weight precontraction (independent of af)
        k_wsd<<<cdiv(din * 8 * 32, T), T>>>(W[L], As[L], Ad[L], din, C, HC);

        // L==0 fused path: repack W into B2 (independent, launch early)
        if (L == 0)
            k_repack_b2<<<cdiv(8 * dinp * C, T), T>>>(W[L], din, dinp, C, HC);

        // concat af + es/ed in one pass
        Cat5 cs;
        int cnt = 0;
        if (L == 0) {
            cs.p[0] = data; cs.w[0] = 2; cs.st[0] = 10;
            cs.p[1] = p_f;  cs.w[1] = 256; cs.st[1] = 256;
            cnt = 2;
        } else if (L == 1) {
            cs.p[0] = p_c1; cs.w[0] = 2; cs.st[0] = 2;
            cs.p[1] = data; cs.w[1] = 2; cs.st[1] = 10;
            cs.p[2] = p_f;  cs.w[2] = 512; cs.st[2] = 512;
            cnt = 3;
        } else if (L == 2) {
            cs.p[0] = p_c2; cs.w[0] = 2; cs.st[0] = 2;
            cs.p[1] = p_c1; cs.w[1] = 2; cs.st[1] = 2;
            cs.p[2] = data; cs.w[2] = 2; cs.st[2] = 10;
            cs.p[3] = p_f;  cs.w[3] = 256; cs.st[3] = 256;
            cnt = 4;
        } else {
            cs.p[0] = p_c3; cs.w[0] = 2; cs.st[0] = 2;
            cs.p[1] = p_c2; cs.w[1] = 2; cs.st[1] = 2;
            cs.p[2] = p_c1; cs.w[2] = 2; cs.st[2] = 2;
            cs.p[3] = data; cs.w[3] = 2; cs.st[3] = 10;
            cs.p[4] = p_f;  cs.w[4] = 128; cs.st[4] = 128;
            cnt = 5;
        }
        for (int s = cnt; s < 5; s++) { cs.p[s] = data; cs.w[s] = 0; cs.st[s] = 0; }
        k_cat_esed<<<n, 256>>>(cs, cnt, din, dinp, n);

        if (L >= 1 && L < 3) {
            // old path: h = af @ W (overlaps with softmax below)
            dim3 grid(HC / BN, cdiv(n, BM));
            k_mma_gemm<<<grid, 256, GEMM_SMEM>>>(p_af, W[L], p_h, n, dinp, din, HC,
                                                 0, nullptr);
        }

        // fused segment softmax + coordinate update
        k_softmax_coord<<<cdiv(n, 8), 256>>>(dinp, n, couts[L]);

        if (L == 0) {
            // fused path: aggregate af, then single GEMM with selu epilogue
            k_agg_af<<<n, dinp>>>(dinp, n);
            int K2 = 8 * dinp;                        // 2304
            dim3 grid(C / BN, cdiv(n, BM));           // 4 x 40
            k_mma_gemm<<<grid, 256, GEMM_SMEM>>>(p_h, p_b2, p_f, n, K2, K2, C,
                                                 1, Bi[L]);
        } else if (L < 3) {
            int bt = C / 4 < 128 ? C / 4 : 128;
            dim3 grid(cdiv(C / 4, bt), n);
            k_feat_agg<<<grid, bt>>>(Bi[L], C, n, HC);
        }
    }
}